// round 1
// baseline (speedup 1.0000x reference)
#include <cuda_runtime.h>

#define BATCH 128
#define CH 256
#define HW 3136          // 56*56
#define PFD 8            // per-filter dim
#define KDIM 2048        // CH*PFD
#define JH 256           // final hidden
#define NCLS 1000
#define KSPLIT 16        // k-splits for gemm2
#define JTILES 8         // 256/32

// Scratch (allocation-free rule: __device__ globals)
__device__ float g_concat[BATCH * KDIM];            // 1 MB
__device__ float g_hpart[KSPLIT * BATCH * JH];      // 2 MB, deterministic split-K partials

// ---------------------------------------------------------------------------
// Kernel 1: global average pool fused with per-channel Linear(1->8)+ReLU.
// One warp per (b,c) pair. 411 MB of reads -> HBM-bound; everything vectorized.
// ---------------------------------------------------------------------------
__global__ void __launch_bounds__(256) pool_kernel(const float* __restrict__ x,
                                                   const float* __restrict__ W1,
                                                   const float* __restrict__ b1) {
    int warp = threadIdx.x >> 5;
    int lane = threadIdx.x & 31;
    int pair = blockIdx.x * 8 + warp;        // pair = b*CH + c, in [0, 32768)
    const float4* xv = (const float4*)(x + (long)pair * HW);

    float s = 0.f;
    #pragma unroll 4
    for (int it = lane; it < HW / 4; it += 32) {   // 784 float4 per pair
        float4 v = xv[it];
        s += (v.x + v.y) + (v.z + v.w);
    }
    #pragma unroll
    for (int off = 16; off; off >>= 1)
        s += __shfl_xor_sync(0xffffffffu, s, off);

    float p = s * (1.0f / 3136.0f);          // mean, present in all lanes
    int b = pair >> 8;
    int c = pair & 255;
    if (lane < PFD) {
        float v = fmaf(p, W1[c * PFD + lane], b1[c * PFD + lane]);
        g_concat[b * KDIM + c * PFD + lane] = fmaxf(v, 0.f);
    }
}

// ---------------------------------------------------------------------------
// Kernel 2: h_partial[ks][b][j] = sum_{k in slice ks} concat[b][k] * W2[j][k]
// Grid = KSPLIT*JTILES = 128 blocks (covers the chip). Block computes a
// [128 b x 32 j] tile over a K-slice of 128 (two 64-wide smem tiles).
// 4x4 register blocking; smem row stride 68 keeps loads float4-aligned and
// conflict-free for this thread mapping. No atomics: deterministic.
// ---------------------------------------------------------------------------
__global__ void __launch_bounds__(256) gemm2_kernel(const float* __restrict__ W2) {
    __shared__ float cs[BATCH * 68];   // concat tile [128][64] (stride 68)
    __shared__ float ws[32 * 68];      // W2 tile     [32][64]  (stride 68)

    int jt = blockIdx.x & 7;           // j-tile
    int ks = blockIdx.x >> 3;          // k-split
    int j0 = jt * 32;
    int t = threadIdx.x;
    int jgrp  = t & 7;                 // j = j0 + jgrp + 8*jjj
    int bbase = t >> 3;                // b = bbase + 32*bi

    float acc[4][4];
    #pragma unroll
    for (int a = 0; a < 4; a++)
        #pragma unroll
        for (int b = 0; b < 4; b++) acc[a][b] = 0.f;

    #pragma unroll
    for (int kt = 0; kt < 2; kt++) {
        int kb = ks * 128 + kt * 64;

        // Load concat tile: 2048 float4, 8 per thread, fully coalesced.
        #pragma unroll
        for (int i = 0; i < 8; i++) {
            int f = t + 256 * i;
            int bb = f >> 4, kq = f & 15;
            float4 v = *(const float4*)(g_concat + bb * KDIM + kb + kq * 4);
            *(float4*)(cs + bb * 68 + kq * 4) = v;
        }
        // Load W2 tile: 512 float4, 2 per thread.
        #pragma unroll
        for (int i = 0; i < 2; i++) {
            int f = t + 256 * i;
            int jj = f >> 4, kq = f & 15;
            float4 v = *(const float4*)(W2 + (long)(j0 + jj) * KDIM + kb + kq * 4);
            *(float4*)(ws + jj * 68 + kq * 4) = v;
        }
        __syncthreads();

        #pragma unroll 4
        for (int k = 0; k < 64; k++) {
            float wv[4], cv[4];
            #pragma unroll
            for (int jjj = 0; jjj < 4; jjj++) wv[jjj] = ws[(jgrp + 8 * jjj) * 68 + k];
            #pragma unroll
            for (int bi = 0; bi < 4; bi++)    cv[bi] = cs[(bbase + 32 * bi) * 68 + k];
            #pragma unroll
            for (int jjj = 0; jjj < 4; jjj++)
                #pragma unroll
                for (int bi = 0; bi < 4; bi++)
                    acc[jjj][bi] = fmaf(wv[jjj], cv[bi], acc[jjj][bi]);
        }
        __syncthreads();
    }

    // Store 16 partials per thread.
    #pragma unroll
    for (int jjj = 0; jjj < 4; jjj++) {
        int j = j0 + jgrp + 8 * jjj;
        #pragma unroll
        for (int bi = 0; bi < 4; bi++) {
            int b = bbase + 32 * bi;
            g_hpart[(ks * BATCH + b) * JH + j] = acc[jjj][bi];
        }
    }
}

// ---------------------------------------------------------------------------
// Kernel 3: out[b][n] = sum_j relu(sum_ks hpart[ks][b][j] + b2[j]) * W3[n][j] + b3[n]
// Block = 8 batches x 128 classes; grid = 16 x 8 = 128 blocks.
// h is reduced + biased + ReLU'd into smem once per block; W3 stays in L2/L1.
// ---------------------------------------------------------------------------
__global__ void __launch_bounds__(128) gemm3_kernel(const float* __restrict__ b2,
                                                    const float* __restrict__ W3,
                                                    const float* __restrict__ b3,
                                                    float* __restrict__ out) {
    __shared__ float hs[8 * JH];
    int b0 = (blockIdx.x >> 3) * 8;
    int n0 = (blockIdx.x & 7) * 128;
    int t = threadIdx.x;

    // Build hs: reduce the 16 split-K partials, add bias, ReLU. Coalesced.
    #pragma unroll
    for (int i = 0; i < 16; i++) {
        int lin = t + 128 * i;           // 2048 elements
        int bb = lin >> 8, j = lin & 255;
        float v = b2[j];
        #pragma unroll
        for (int ksx = 0; ksx < KSPLIT; ksx++)
            v += g_hpart[(ksx * BATCH + b0 + bb) * JH + j];
        hs[lin] = fmaxf(v, 0.f);
    }
    __syncthreads();

    int n = n0 + t;
    if (n < NCLS) {
        float acc[8];
        #pragma unroll
        for (int bb = 0; bb < 8; bb++) acc[bb] = 0.f;
        const float* wr = W3 + (long)n * JH;
        #pragma unroll 4
        for (int j = 0; j < JH; j++) {
            float w = wr[j];
            #pragma unroll
            for (int bb = 0; bb < 8; bb++)
                acc[bb] = fmaf(w, hs[bb * JH + j], acc[bb]);
        }
        float bn = b3[n];
        #pragma unroll
        for (int bb = 0; bb < 8; bb++)
            out[(long)(b0 + bb) * NCLS + n] = acc[bb] + bn;
    }
}

// ---------------------------------------------------------------------------
extern "C" void kernel_launch(void* const* d_in, const int* in_sizes, int n_in,
                              void* d_out, int out_size) {
    const float* x  = (const float*)d_in[0];
    const float* W1 = (const float*)d_in[1];
    const float* b1 = (const float*)d_in[2];
    const float* W2 = (const float*)d_in[3];
    const float* b2 = (const float*)d_in[4];
    const float* W3 = (const float*)d_in[5];
    const float* b3 = (const float*)d_in[6];
    float* out = (float*)d_out;

    pool_kernel<<<(BATCH * CH) / 8, 256>>>(x, W1, b1);        // 4096 blocks
    gemm2_kernel<<<KSPLIT * JTILES, 256>>>(W2);               // 128 blocks
    gemm3_kernel<<<(BATCH / 8) * 8, 128>>>(b2, W3, b3, out);  // 128 blocks
}

// round 4
// speedup vs baseline: 1.1623x; 1.1623x over previous
#include <cuda_runtime.h>

#define BATCH 128
#define CH 256
#define HW 3136          // 56*56
#define PFD 8            // per-filter dim
#define KDIM 2048        // CH*PFD
#define JH 256           // final hidden
#define NCLS 1000
#define KSPLIT 16        // k-splits for gemm2
#define JTILES 8         // 256/32

// Scratch (allocation-free rule: __device__ globals)
__device__ float g_concat[BATCH * KDIM];            // 1 MB
__device__ float g_hpart[KSPLIT * BATCH * JH];      // 2 MB, deterministic split-K partials
__device__ float g_h[BATCH * JH];                   // 128 KB, reduced+bias+relu hidden

// ---------------------------------------------------------------------------
// Kernel 1: global average pool fused with per-channel Linear(1->8)+ReLU.
// One warp per (b,c) pair; 8 front-batched float4 LDGs per chunk (MLP=8).
// ---------------------------------------------------------------------------
__global__ void __launch_bounds__(512) pool_kernel(const float* __restrict__ x,
                                                   const float* __restrict__ W1,
                                                   const float* __restrict__ b1) {
    int warp = threadIdx.x >> 5;
    int lane = threadIdx.x & 31;
    int pair = blockIdx.x * 16 + warp;       // pair = b*CH + c, in [0, 32768)
    const float4* xv = (const float4*)(x + (long)pair * HW);

    float s0 = 0.f, s1 = 0.f, s2 = 0.f, s3 = 0.f;
    // 784 float4 per pair = 3 chunks of 8x32 + tail of 16
    #pragma unroll
    for (int c = 0; c < 3; c++) {
        float4 v[8];
        #pragma unroll
        for (int u = 0; u < 8; u++)
            v[u] = xv[lane + 32 * u + 256 * c];
        #pragma unroll
        for (int u = 0; u < 8; u += 4) {
            s0 += v[u].x + v[u].y;         s1 += v[u].z + v[u].w;
            s2 += v[u+1].x + v[u+1].y;     s3 += v[u+1].z + v[u+1].w;
            s0 += v[u+2].x + v[u+2].y;     s1 += v[u+2].z + v[u+2].w;
            s2 += v[u+3].x + v[u+3].y;     s3 += v[u+3].z + v[u+3].w;
        }
    }
    if (lane < 16) {
        float4 v = xv[768 + lane];
        s0 += v.x + v.y; s1 += v.z + v.w;
    }
    float s = (s0 + s1) + (s2 + s3);
    #pragma unroll
    for (int off = 16; off; off >>= 1)
        s += __shfl_xor_sync(0xffffffffu, s, off);

    float p = s * (1.0f / 3136.0f);          // mean, present in all lanes
    int b = pair >> 8;
    int c = pair & 255;
    if (lane < PFD) {
        float v = fmaf(p, W1[c * PFD + lane], b1[c * PFD + lane]);
        g_concat[b * KDIM + c * PFD + lane] = fmaxf(v, 0.f);
    }
}

// ---------------------------------------------------------------------------
// Kernel 2: h_partial[ks][b][j] = sum_{k in slice ks} concat[b][k] * W2[j][k]
// 128 blocks, [128b x 32j] tile per K-slice of 128. 4x4 register blocking.
// ---------------------------------------------------------------------------
__global__ void __launch_bounds__(256) gemm2_kernel(const float* __restrict__ W2) {
    __shared__ float cs[BATCH * 68];   // concat tile [128][64] (stride 68)
    __shared__ float ws[32 * 68];      // W2 tile     [32][64]  (stride 68)

    int jt = blockIdx.x & 7;           // j-tile
    int ks = blockIdx.x >> 3;          // k-split
    int j0 = jt * 32;
    int t = threadIdx.x;
    int jgrp  = t & 7;                 // j = j0 + jgrp + 8*jjj
    int bbase = t >> 3;                // b = bbase + 32*bi

    float acc[4][4];
    #pragma unroll
    for (int a = 0; a < 4; a++)
        #pragma unroll
        for (int b = 0; b < 4; b++) acc[a][b] = 0.f;

    #pragma unroll
    for (int kt = 0; kt < 2; kt++) {
        int kb = ks * 128 + kt * 64;

        #pragma unroll
        for (int i = 0; i < 8; i++) {
            int f = t + 256 * i;
            int bb = f >> 4, kq = f & 15;
            float4 v = *(const float4*)(g_concat + bb * KDIM + kb + kq * 4);
            *(float4*)(cs + bb * 68 + kq * 4) = v;
        }
        #pragma unroll
        for (int i = 0; i < 2; i++) {
            int f = t + 256 * i;
            int jj = f >> 4, kq = f & 15;
            float4 v = *(const float4*)(W2 + (long)(j0 + jj) * KDIM + kb + kq * 4);
            *(float4*)(ws + jj * 68 + kq * 4) = v;
        }
        __syncthreads();

        #pragma unroll 4
        for (int k = 0; k < 64; k++) {
            float wv[4], cv[4];
            #pragma unroll
            for (int jjj = 0; jjj < 4; jjj++) wv[jjj] = ws[(jgrp + 8 * jjj) * 68 + k];
            #pragma unroll
            for (int bi = 0; bi < 4; bi++)    cv[bi] = cs[(bbase + 32 * bi) * 68 + k];
            #pragma unroll
            for (int jjj = 0; jjj < 4; jjj++)
                #pragma unroll
                for (int bi = 0; bi < 4; bi++)
                    acc[jjj][bi] = fmaf(wv[jjj], cv[bi], acc[jjj][bi]);
        }
        __syncthreads();
    }

    #pragma unroll
    for (int jjj = 0; jjj < 4; jjj++) {
        int j = j0 + jgrp + 8 * jjj;
        #pragma unroll
        for (int bi = 0; bi < 4; bi++) {
            int b = bbase + 32 * bi;
            g_hpart[(ks * BATCH + b) * JH + j] = acc[jjj][bi];
        }
    }
}

// ---------------------------------------------------------------------------
// Kernel 2.5: g_h[b][j] = relu(b2[j] + sum_ks hpart[ks][b][j]).  One pass.
// ---------------------------------------------------------------------------
__global__ void __launch_bounds__(256) reduceh_kernel(const float* __restrict__ b2) {
    int lin = blockIdx.x * 256 + threadIdx.x;   // 32768 elements
    int j = lin & 255;
    float v = b2[j];
    #pragma unroll
    for (int ks = 0; ks < KSPLIT; ks++)
        v += g_hpart[ks * (BATCH * JH) + lin];
    g_h[lin] = fmaxf(v, 0.f);
}

// ---------------------------------------------------------------------------
// Kernel 3: out[b][n] = sum_j g_h[b][j] * W3[n][j] + b3[n]
// Block tile [32b x 128n], 256 threads, 4b x 4n per thread. j tiled x8 at 32.
// W3 staged in natural [n][j] layout, odd stride 33:
//   - compute reads ws[(q*32+tn)*33 + j]: bank = tn -> conflict-free
//   - hs reads are warp-uniform -> broadcast
// smem total = (128+32)*33*4 = 21120 B.  Grid = 4 x 8 = 32 blocks.
// ---------------------------------------------------------------------------
__global__ void __launch_bounds__(256) gemm3_kernel(const float* __restrict__ W3,
                                                    const float* __restrict__ b3,
                                                    float* __restrict__ out) {
    __shared__ float ws[128 * 33];     // W3 tile [128n][32j], stride 33
    __shared__ float hs[32 * 33];      // h tile  [32b][32j],  stride 33

    int b0 = (blockIdx.x >> 3) * 32;
    int n0 = (blockIdx.x & 7) * 128;
    int t = threadIdx.x;
    int tn = t & 31;                   // n lane
    int tb = t >> 5;                   // b group 0..7

    float acc[4][4];
    #pragma unroll
    for (int r = 0; r < 4; r++)
        #pragma unroll
        for (int q = 0; q < 4; q++) acc[r][q] = 0.f;

    for (int jt = 0; jt < 8; jt++) {   // j tiles of 32
        // Stage W3 tile [128n x 32j]: 1024 float4, 4 per thread, coalesced.
        #pragma unroll
        for (int i = 0; i < 4; i++) {
            int f = t + 256 * i;
            int row = f >> 3;          // n offset 0..127
            int c4 = f & 7;            // j quad 0..7
            float4 v = make_float4(0.f, 0.f, 0.f, 0.f);
            if (n0 + row < NCLS)
                v = *(const float4*)(W3 + (long)(n0 + row) * JH + jt * 32 + c4 * 4);
            float* wp = ws + row * 33 + c4 * 4;
            wp[0] = v.x; wp[1] = v.y; wp[2] = v.z; wp[3] = v.w;
        }
        // Stage h tile [32b x 32j]: 1024 floats, 4 per thread, coalesced.
        #pragma unroll
        for (int i = 0; i < 4; i++) {
            int f = t + 256 * i;
            int bb = f >> 5, j = f & 31;
            hs[bb * 33 + j] = g_h[(b0 + bb) * JH + jt * 32 + j];
        }
        __syncthreads();

        #pragma unroll 4
        for (int j = 0; j < 32; j++) {
            float wv[4], hv[4];
            #pragma unroll
            for (int q = 0; q < 4; q++) wv[q] = ws[(q * 32 + tn) * 33 + j];
            #pragma unroll
            for (int r = 0; r < 4; r++) hv[r] = hs[(tb * 4 + r) * 33 + j];
            #pragma unroll
            for (int r = 0; r < 4; r++)
                #pragma unroll
                for (int q = 0; q < 4; q++)
                    acc[r][q] = fmaf(hv[r], wv[q], acc[r][q]);
        }
        __syncthreads();
    }

    #pragma unroll
    for (int q = 0; q < 4; q++) {
        int n = n0 + q * 32 + tn;
        if (n < NCLS) {
            float bn = b3[n];
            #pragma unroll
            for (int r = 0; r < 4; r++)
                out[(long)(b0 + tb * 4 + r) * NCLS + n] = acc[r][q] + bn;
        }
    }
}

// ---------------------------------------------------------------------------
extern "C" void kernel_launch(void* const* d_in, const int* in_sizes, int n_in,
                              void* d_out, int out_size) {
    const float* x  = (const float*)d_in[0];
    const float* W1 = (const float*)d_in[1];
    const float* b1 = (const float*)d_in[2];
    const float* W2 = (const float*)d_in[3];
    const float* b2 = (const float*)d_in[4];
    const float* W3 = (const float*)d_in[5];
    const float* b3 = (const float*)d_in[6];
    float* out = (float*)d_out;

    pool_kernel<<<(BATCH * CH) / 16, 512>>>(x, W1, b1);       // 2048 blocks
    gemm2_kernel<<<KSPLIT * JTILES, 256>>>(W2);               // 128 blocks
    reduceh_kernel<<<(BATCH * JH) / 256, 256>>>(b2);          // 128 blocks
    gemm3_kernel<<<32, 256>>>(W3, b3, out);                   // 32 blocks
}